// round 6
// baseline (speedup 1.0000x reference)
#include <cuda_runtime.h>
#include <cuda_bf16.h>
#include <math.h>
#include <stdint.h>

// ---------------------------------------------------------------------------
// Problem constants
// ---------------------------------------------------------------------------
#define BB 2
#define SS 1024
#define WW 64
#define PP (SS + WW - 1)   // 1087
#define EE 256
#define FIN 64
#define FF 1024
#define TE 768
#define NH 8
#define HD 32
#define NWIN (BB * SS)     // 2048
#define NROW (NWIN * WW)   // 131072
#define OUTD 10
#define LN_EPS 1e-5f
#define ATT_SCALE 0.17677669529663687f

// ---------------------------------------------------------------------------
// Scratch
// ---------------------------------------------------------------------------
__device__ float g_emb  [BB * PP * EE];
__device__ float g_qkv  [BB * PP * TE];
__device__ float g_bufA [(size_t)NROW * EE];
__device__ float g_bufB [(size_t)NROW * EE];
__device__ float g_bufC [(size_t)NROW * FF];   // FFN hidden; later KV2 (stride 512)
__device__ float g_xlast[NWIN * EE];
__device__ float g_r1   [NWIN * EE];
__device__ float g_r2   [NWIN * EE];
__device__ float g_r3   [NWIN * FF];

// ---------------------------------------------------------------------------
// Common MMA helpers
// ---------------------------------------------------------------------------
__device__ __forceinline__ uint32_t f2tf(float f) {
    uint32_t r;
    asm("cvt.rna.tf32.f32 %0, %1;" : "=r"(r) : "f"(f));
    return r;
}

__device__ __forceinline__ void mma_tf32(float* c, const uint32_t* a, const uint32_t* b) {
    asm volatile(
        "mma.sync.aligned.m16n8k8.row.col.f32.tf32.tf32.f32 "
        "{%0,%1,%2,%3},{%4,%5,%6,%7},{%8,%9},{%0,%1,%2,%3};"
        : "+f"(c[0]), "+f"(c[1]), "+f"(c[2]), "+f"(c[3])
        : "r"(a[0]), "r"(a[1]), "r"(a[2]), "r"(a[3]), "r"(b[0]), "r"(b[1]));
}

__device__ __forceinline__ void cp16(void* s, const void* g) {
    uint32_t sa = (uint32_t)__cvta_generic_to_shared(s);
    asm volatile("cp.async.cg.shared.global [%0], [%1], 16;" :: "r"(sa), "l"(g));
}

// ---------------------------------------------------------------------------
// TF32 tensor-core GEMM (NT): C[m,n] = act(sum_k A[m,k]*B[n,k] + bias[n])
// 128x128 tile, BK=16, 3-stage cp.async pipeline, 8 warps, warp tile 64x32.
// Fragment k-permutation: lane t4 carries physical k pair (2*t4, 2*t4+1) in
// both A and B fragments (valid: dot order irrelevant) -> float2 smem loads.
// Requires: K % 16 == 0, N % 128 == 0, K >= 48. act: 0 none, 1 silu.
// ---------------------------------------------------------------------------
#define TBK 16
#define SMS 20
#define NSTAGE 3
#define TG_SMEM (NSTAGE * 2 * 128 * SMS * 4)

extern __shared__ float dynsm[];

__global__ __launch_bounds__(256) void tgemm(
    const float* __restrict__ A, const float* __restrict__ B,
    const float* __restrict__ bias, float* __restrict__ C,
    int M, int N, int K, int lda, int ldb, int ldc, int act) {
    float* Asb = dynsm;                           // [NSTAGE][128][SMS]
    float* Bsb = dynsm + NSTAGE * 128 * SMS;
#define ASM_(st, r, c) Asb[((st) * 128 + (r)) * SMS + (c)]
#define BSM_(st, r, c) Bsb[((st) * 128 + (r)) * SMS + (c)]
    const int tid = threadIdx.x;
    const int bm = blockIdx.y * 128, bn = blockIdx.x * 128;
    const int lane = tid & 31, wid = tid >> 5;
    const int wm = (wid >> 2) * 64, wn = (wid & 3) * 32;
    const int g = lane >> 2, t4 = lane & 3;

    float acc[4][4][4];
#pragma unroll
    for (int i = 0; i < 4; i++)
#pragma unroll
        for (int j = 0; j < 4; j++)
#pragma unroll
            for (int k = 0; k < 4; k++) acc[i][j][k] = 0.f;

    const int T = K / TBK;
    const int r0i = tid >> 2, c4i = (tid & 3) << 2;
    const int r1i = (tid + 256) >> 2, c4i2 = ((tid + 256) & 3) << 2;
    int gcl0 = bm + r0i; if (gcl0 >= M) gcl0 = M - 1;
    int gcl1 = bm + r1i; if (gcl1 >= M) gcl1 = M - 1;

    // prologue: stages 0,1
#pragma unroll
    for (int t = 0; t < 2; t++) {
        const int k0 = t * TBK;
        cp16(&ASM_(t, r0i, c4i),  A + (size_t)gcl0 * lda + k0 + c4i);
        cp16(&ASM_(t, r1i, c4i2), A + (size_t)gcl1 * lda + k0 + c4i2);
        cp16(&BSM_(t, r0i, c4i),  B + (size_t)(bn + r0i) * ldb + k0 + c4i);
        cp16(&BSM_(t, r1i, c4i2), B + (size_t)(bn + r1i) * ldb + k0 + c4i2);
        asm volatile("cp.async.commit_group;");
    }

    for (int t = 0; t < T; t++) {
        if (t + 1 < T) asm volatile("cp.async.wait_group 1;");
        else           asm volatile("cp.async.wait_group 0;");
        __syncthreads();

        if (t + 2 < T) {
            const int st = (t + 2) % NSTAGE;
            const int k0 = (t + 2) * TBK;
            cp16(&ASM_(st, r0i, c4i),  A + (size_t)gcl0 * lda + k0 + c4i);
            cp16(&ASM_(st, r1i, c4i2), A + (size_t)gcl1 * lda + k0 + c4i2);
            cp16(&BSM_(st, r0i, c4i),  B + (size_t)(bn + r0i) * ldb + k0 + c4i);
            cp16(&BSM_(st, r1i, c4i2), B + (size_t)(bn + r1i) * ldb + k0 + c4i2);
            asm volatile("cp.async.commit_group;");
        }

        const int cur = t % NSTAGE;
#pragma unroll
        for (int ks = 0; ks < 2; ks++) {
            const int kb = ks * 8 + 2 * t4;   // physical k pair (kb, kb+1)
            uint32_t af[4][4], bf[4][2];
#pragma unroll
            for (int mt = 0; mt < 4; mt++) {
                const int r = wm + mt * 16;
                float2 v0 = *(float2*)&ASM_(cur, r + g, kb);
                float2 v1 = *(float2*)&ASM_(cur, r + g + 8, kb);
                af[mt][0] = f2tf(v0.x); af[mt][2] = f2tf(v0.y);
                af[mt][1] = f2tf(v1.x); af[mt][3] = f2tf(v1.y);
            }
#pragma unroll
            for (int nt = 0; nt < 4; nt++) {
                float2 v = *(float2*)&BSM_(cur, wn + nt * 8 + g, kb);
                bf[nt][0] = f2tf(v.x); bf[nt][1] = f2tf(v.y);
            }
#pragma unroll
            for (int mt = 0; mt < 4; mt++)
#pragma unroll
                for (int nt = 0; nt < 4; nt++)
                    mma_tf32(acc[mt][nt], af[mt], bf[nt]);
        }
    }

    // epilogue
#pragma unroll
    for (int mt = 0; mt < 4; mt++) {
        const int rA = bm + wm + mt * 16 + g;
        const int rB = rA + 8;
#pragma unroll
        for (int nt = 0; nt < 4; nt++) {
            const int c = bn + wn + nt * 8 + 2 * t4;
            const float b0 = bias ? bias[c] : 0.f;
            const float b1 = bias ? bias[c + 1] : 0.f;
            float v0 = acc[mt][nt][0] + b0, v1 = acc[mt][nt][1] + b1;
            float v2 = acc[mt][nt][2] + b0, v3 = acc[mt][nt][3] + b1;
            if (act == 1) {
                v0 = v0 / (1.f + __expf(-v0));
                v1 = v1 / (1.f + __expf(-v1));
                v2 = v2 / (1.f + __expf(-v2));
                v3 = v3 / (1.f + __expf(-v3));
            }
            if (rA < M) { float2 p = make_float2(v0, v1); *(float2*)&C[(size_t)rA * ldc + c] = p; }
            if (rB < M) { float2 p = make_float2(v2, v3); *(float2*)&C[(size_t)rB * ldc + c] = p; }
        }
    }
}

// ---------------------------------------------------------------------------
// Zero pad rows of g_emb (positions 0..W-2 per batch)
// ---------------------------------------------------------------------------
__global__ void zero_pad_kernel() {
    int idx = blockIdx.x * blockDim.x + threadIdx.x;
    if (idx >= BB * (WW - 1) * EE) return;
    int e = idx & (EE - 1);
    int p = (idx >> 8) % (WW - 1);
    int b = idx / ((WW - 1) * EE);
    g_emb[((size_t)b * PP + p) * EE + e] = 0.f;
}

// ---------------------------------------------------------------------------
// Layer-1 attention via tensor cores. One block (128 thr, 4 warps) per (n,h).
// scores = Q K^T (64x64x32), softmax, O = P V (64x32x64); all mma tf32.
// ---------------------------------------------------------------------------
#define QS(r, c) s_q[(r) * 33 + (c)]
#define KS(r, c) s_k[(r) * 33 + (c)]
#define VS(r, c) s_v[(r) * 33 + (c)]
#define SC(r, c) s_s[(r) * 66 + (c)]

__global__ __launch_bounds__(128) void attn1_kernel(const float* __restrict__ qkv,
                                                    float* __restrict__ out) {
    __shared__ float s_q[WW * 33], s_k[WW * 33], s_v[WW * 33];
    __shared__ float s_s[WW * 66];
    const int h = blockIdx.x;
    const int n = blockIdx.y;
    const int b = n >> 10, s = n & (SS - 1);
    const int tid = threadIdx.x;
    const int lane = tid & 31, w = tid >> 5;
    const int g = lane >> 2, t4 = lane & 3;

    size_t base = ((size_t)b * PP + s) * TE + h * HD;
    for (int t = tid; t < WW * HD; t += 128) {
        int wpos = t >> 5, d = t & 31;
        size_t r = base + (size_t)wpos * TE + d;
        QS(wpos, d) = qkv[r];
        KS(wpos, d) = qkv[r + EE];
        VS(wpos, d) = qkv[r + 2 * EE];
    }
    __syncthreads();

    // scores: warp w -> rows 16w..16w+15, all 64 cols
    {
        float sacc[8][4];
#pragma unroll
        for (int i = 0; i < 8; i++)
#pragma unroll
            for (int j = 0; j < 4; j++) sacc[i][j] = 0.f;
#pragma unroll
        for (int k0 = 0; k0 < HD; k0 += 8) {
            uint32_t a[4];
            a[0] = f2tf(QS(16 * w + g, k0 + t4));
            a[1] = f2tf(QS(16 * w + g + 8, k0 + t4));
            a[2] = f2tf(QS(16 * w + g, k0 + t4 + 4));
            a[3] = f2tf(QS(16 * w + g + 8, k0 + t4 + 4));
#pragma unroll
            for (int nt = 0; nt < 8; nt++) {
                uint32_t bfr[2];
                bfr[0] = f2tf(KS(nt * 8 + g, k0 + t4));
                bfr[1] = f2tf(KS(nt * 8 + g, k0 + t4 + 4));
                mma_tf32(sacc[nt], a, bfr);
            }
        }
#pragma unroll
        for (int nt = 0; nt < 8; nt++) {
            const int r0 = 16 * w + g, c = nt * 8 + 2 * t4;
            float2 p0 = make_float2(sacc[nt][0] * ATT_SCALE, sacc[nt][1] * ATT_SCALE);
            float2 p1 = make_float2(sacc[nt][2] * ATT_SCALE, sacc[nt][3] * ATT_SCALE);
            *(float2*)&SC(r0, c) = p0;
            *(float2*)&SC(r0 + 8, c) = p1;
        }
    }
    __syncthreads();

    // softmax: thread pair per row (64 rows, 2 lanes x 32 cols)
    {
        const int row = tid >> 1, half = tid & 1;
        const int cb = half * 32;
        float mx = -1e30f;
#pragma unroll
        for (int j = 0; j < 32; j++) mx = fmaxf(mx, SC(row, cb + j));
        mx = fmaxf(mx, __shfl_xor_sync(0xffffffff, mx, 1));
        float sum = 0.f;
#pragma unroll
        for (int j = 0; j < 32; j++) {
            float e = __expf(SC(row, cb + j) - mx);
            SC(row, cb + j) = e;
            sum += e;
        }
        sum += __shfl_xor_sync(0xffffffff, sum, 1);
        float inv = 1.f / sum;
#pragma unroll
        for (int j = 0; j < 32; j++) SC(row, cb + j) *= inv;
    }
    __syncthreads();

    // O = P V: m=64 (warp rows 16w..), n=32 (head dim), k=64
    {
        float oacc[4][4];
#pragma unroll
        for (int i = 0; i < 4; i++)
#pragma unroll
            for (int j = 0; j < 4; j++) oacc[i][j] = 0.f;
#pragma unroll
        for (int k0 = 0; k0 < WW; k0 += 8) {
            uint32_t a[4];
            a[0] = f2tf(SC(16 * w + g, k0 + t4));
            a[1] = f2tf(SC(16 * w + g + 8, k0 + t4));
            a[2] = f2tf(SC(16 * w + g, k0 + t4 + 4));
            a[3] = f2tf(SC(16 * w + g + 8, k0 + t4 + 4));
#pragma unroll
            for (int nt = 0; nt < 4; nt++) {
                uint32_t bfr[2];
                bfr[0] = f2tf(VS(k0 + t4, nt * 8 + g));
                bfr[1] = f2tf(VS(k0 + t4 + 4, nt * 8 + g));
                mma_tf32(oacc[nt], a, bfr);
            }
        }
        const size_t row0 = ((size_t)n * WW + 16 * w + g) * EE + h * HD;
        const size_t row1 = row0 + 8 * EE;
#pragma unroll
        for (int nt = 0; nt < 4; nt++) {
            const int c = nt * 8 + 2 * t4;
            *(float2*)&out[row0 + c] = make_float2(oacc[nt][0], oacc[nt][1]);
            *(float2*)&out[row1 + c] = make_float2(oacc[nt][2], oacc[nt][3]);
        }
    }
}

// ---------------------------------------------------------------------------
// Layer-2 attention (pruned): Q from compact [2048,256], KV from [NROW,512].
// ---------------------------------------------------------------------------
__global__ __launch_bounds__(64) void attn2_kernel(const float* __restrict__ q2,
                                                   const float* __restrict__ kv,
                                                   float* __restrict__ out) {
    int h = blockIdx.x;
    int n = blockIdx.y;
    int tid = threadIdx.x;
    __shared__ float ks[WW][HD + 1], vs[WW][HD + 1];
    __shared__ float q[HD], p[WW];

    size_t base = (size_t)n * WW * 512 + h * HD;
    for (int t = tid; t < WW * HD; t += 64) {
        int wpos = t >> 5, d = t & 31;
        size_t r = base + (size_t)wpos * 512 + d;
        ks[wpos][d] = kv[r];
        vs[wpos][d] = kv[r + 256];
    }
    if (tid < HD) q[tid] = q2[(size_t)n * EE + h * HD + tid];
    __syncthreads();

    {
        float dsum = 0.f;
#pragma unroll
        for (int d = 0; d < HD; d++) dsum = fmaf(q[d], ks[tid][d], dsum);
        p[tid] = dsum * ATT_SCALE;
    }
    __syncthreads();
    if (tid < 32) {
        float v = fmaxf(p[tid], p[tid + 32]);
#pragma unroll
        for (int o = 16; o > 0; o >>= 1) v = fmaxf(v, __shfl_xor_sync(0xffffffff, v, o));
        float e0 = __expf(p[tid] - v), e1 = __expf(p[tid + 32] - v);
        float sm = e0 + e1;
#pragma unroll
        for (int o = 16; o > 0; o >>= 1) sm += __shfl_xor_sync(0xffffffff, sm, o);
        float inv = 1.f / sm;
        p[tid] = e0 * inv; p[tid + 32] = e1 * inv;
    }
    __syncthreads();
    if (tid < HD) {
        float acc = 0.f;
#pragma unroll
        for (int j = 0; j < WW; j++) acc = fmaf(p[j], vs[j][tid], acc);
        out[(size_t)n * EE + h * HD + tid] = acc;
    }
}

// ---------------------------------------------------------------------------
// Fused residual-add + LayerNorm (E = 256, 256 threads/row, shuffle reduce).
// mode 0: res row = row; mode 1: res = window view of g_emb.
// ---------------------------------------------------------------------------
__global__ __launch_bounds__(256) void add_ln_kernel(
    const float* __restrict__ a, const float* __restrict__ res,
    const float* __restrict__ gamma, const float* __restrict__ beta,
    float* __restrict__ out, int mode) {
    int row = blockIdx.x;
    int e = threadIdx.x;
    int lane = e & 31, w = e >> 5;
    __shared__ float ws[8];

    size_t roff;
    if (mode == 0) roff = (size_t)row * EE;
    else {
        int n = row >> 6, wp = row & 63;
        int b = n >> 10, s = n & (SS - 1);
        roff = ((size_t)b * PP + s + wp) * EE;
    }

    float x = a[(size_t)row * EE + e] + res[roff + e];

    float s1 = x;
#pragma unroll
    for (int o = 16; o > 0; o >>= 1) s1 += __shfl_xor_sync(0xffffffff, s1, o);
    if (lane == 0) ws[w] = s1;
    __syncthreads();
    float tot = 0.f;
#pragma unroll
    for (int i = 0; i < 8; i++) tot += ws[i];
    float mean = tot * (1.f / EE);
    __syncthreads();

    float d = x - mean;
    float s2 = d * d;
#pragma unroll
    for (int o = 16; o > 0; o >>= 1) s2 += __shfl_xor_sync(0xffffffff, s2, o);
    if (lane == 0) ws[w] = s2;
    __syncthreads();
    float tot2 = 0.f;
#pragma unroll
    for (int i = 0; i < 8; i++) tot2 += ws[i];
    float var = tot2 * (1.f / EE);
    out[(size_t)row * EE + e] = d * rsqrtf(var + LN_EPS) * gamma[e] + beta[e];
}

// ---------------------------------------------------------------------------
// Gather last window rows: x2[(n*64+63)] -> xlast[n]
// ---------------------------------------------------------------------------
__global__ void gather_last_kernel(const float* __restrict__ x2,
                                   float* __restrict__ xlast) {
    int idx = blockIdx.x * blockDim.x + threadIdx.x;
    if (idx >= NWIN * EE) return;
    int n = idx >> 8, e = idx & 255;
    xlast[idx] = x2[((size_t)n * WW + (WW - 1)) * EE + e];
}

// ---------------------------------------------------------------------------
// Head: out[n,o] = y[n] . head_w[o] + head_b[o]
// ---------------------------------------------------------------------------
__global__ void head_kernel(const float* __restrict__ y,
                            const float* __restrict__ hw,
                            const float* __restrict__ hb,
                            float* __restrict__ out) {
    int idx = blockIdx.x * blockDim.x + threadIdx.x;
    if (idx >= NWIN * OUTD) return;
    int n = idx / OUTD, o = idx % OUTD;
    const float* yr = y + (size_t)n * EE;
    const float* wr = hw + (size_t)o * EE;
    float acc = hb[o];
#pragma unroll 8
    for (int k = 0; k < EE; k++) acc = fmaf(yr[k], wr[k], acc);
    out[idx] = acc;
}

// ---------------------------------------------------------------------------
// Host launch
// ---------------------------------------------------------------------------
static inline dim3 tgrid(int M, int N) {
    return dim3(N / 128, (M + 127) / 128);
}

extern "C" void kernel_launch(void* const* d_in, const int* in_sizes, int n_in,
                              void* d_out, int out_size) {
    const float* inputs     = (const float*)d_in[0];
    const float* embed_w    = (const float*)d_in[1];
    const float* embed_b    = (const float*)d_in[2];
    const float* qkv_w      = (const float*)d_in[3];
    const float* qkv_b      = (const float*)d_in[4];
    const float* attn_out_w = (const float*)d_in[5];
    const float* attn_out_b = (const float*)d_in[6];
    const float* ln1_g      = (const float*)d_in[7];
    const float* ln1_b      = (const float*)d_in[8];
    const float* ffn1_w     = (const float*)d_in[9];
    const float* ffn1_b     = (const float*)d_in[10];
    const float* ffn2_w     = (const float*)d_in[11];
    const float* ffn2_b     = (const float*)d_in[12];
    const float* ln2_g      = (const float*)d_in[13];
    const float* ln2_b      = (const float*)d_in[14];
    const float* head_w     = (const float*)d_in[15];
    const float* head_b     = (const float*)d_in[16];
    float* out = (float*)d_out;

    static int smem_set = 0;
    if (!smem_set) {
        cudaFuncSetAttribute(tgemm, cudaFuncAttributeMaxDynamicSharedMemorySize, TG_SMEM);
        smem_set = 1;
    }

    float *emb, *qkv, *bufA, *bufB, *bufC, *xlast, *r1, *r2, *r3;
    cudaGetSymbolAddress((void**)&emb,   g_emb);
    cudaGetSymbolAddress((void**)&qkv,   g_qkv);
    cudaGetSymbolAddress((void**)&bufA,  g_bufA);
    cudaGetSymbolAddress((void**)&bufB,  g_bufB);
    cudaGetSymbolAddress((void**)&bufC,  g_bufC);
    cudaGetSymbolAddress((void**)&xlast, g_xlast);
    cudaGetSymbolAddress((void**)&r1,    g_r1);
    cudaGetSymbolAddress((void**)&r2,    g_r2);
    cudaGetSymbolAddress((void**)&r3,    g_r3);

    // 1. zero pad rows, then embedding GEMMs (one per batch, M=1024)
    zero_pad_kernel<<<(BB * (WW - 1) * EE + 255) / 256, 256>>>();
    for (int b = 0; b < BB; b++) {
        tgemm<<<tgrid(SS, EE), 256, TG_SMEM>>>(inputs + (size_t)b * SS * FIN, embed_w, embed_b,
                                               emb + ((size_t)b * PP + (WW - 1)) * EE,
                                               SS, EE, FIN, FIN, FIN, EE, 0);
    }
    // 2. Layer-1 QKV (shared): [2174,256] x [768,256]^T
    tgemm<<<tgrid(BB * PP, TE), 256, TG_SMEM>>>(emb, qkv_w, qkv_b, qkv,
                                                BB * PP, TE, EE, EE, EE, TE, 0);
    // 3. attention -> bufA [131072,256]
    attn1_kernel<<<dim3(NH, NWIN), 128>>>(qkv, bufA);
    // 4. attn-out proj -> bufB
    tgemm<<<tgrid(NROW, EE), 256, TG_SMEM>>>(bufA, attn_out_w, attn_out_b, bufB,
                                             NROW, EE, EE, EE, EE, EE, 0);
    // 5. x1 = LN1(emb_window + bufB) -> bufA
    add_ln_kernel<<<NROW, 256>>>(bufB, emb, ln1_g, ln1_b, bufA, 1);
    // 6. FFN hidden (silu) -> bufC [131072,1024]
    tgemm<<<tgrid(NROW, FF), 256, TG_SMEM>>>(bufA, ffn1_w, ffn1_b, bufC,
                                             NROW, FF, EE, EE, EE, FF, 1);
    // 7. FFN out -> bufB
    tgemm<<<tgrid(NROW, EE), 256, TG_SMEM>>>(bufC, ffn2_w, ffn2_b, bufB,
                                             NROW, EE, FF, FF, FF, EE, 0);
    // 8. x2 = LN2(x1 + bufB) -> bufA
    add_ln_kernel<<<NROW, 256>>>(bufB, bufA, ln2_g, ln2_b, bufA, 0);

    // ---- Layer 2 (output pruned) ----
    // 9. gather last rows -> xlast; Q only for last rows -> r2
    gather_last_kernel<<<(NWIN * EE + 255) / 256, 256>>>(bufA, xlast);
    tgemm<<<tgrid(NWIN, EE), 256, TG_SMEM>>>(xlast, qkv_w + (size_t)TE * EE, qkv_b + TE,
                                             r2, NWIN, EE, EE, EE, EE, EE, 0);
    // 10. KV for all rows -> bufC [131072,512]
    tgemm<<<tgrid(NROW, 512), 256, TG_SMEM>>>(bufA, qkv_w + (size_t)TE * EE + (size_t)EE * EE,
                                              qkv_b + TE + EE, bufC,
                                              NROW, 512, EE, EE, EE, 512, 0);
    // 11. attention (q last row) -> r1
    attn2_kernel<<<dim3(NH, NWIN), 64>>>(r2, bufC, r1);
    // 12. proj -> r2
    tgemm<<<tgrid(NWIN, EE), 256, TG_SMEM>>>(r1, attn_out_w + (size_t)EE * EE, attn_out_b + EE,
                                             r2, NWIN, EE, EE, EE, EE, EE, 0);
    // 13. y = LN1_l2(xlast + r2) -> r1
    add_ln_kernel<<<NWIN, 256>>>(r2, xlast, ln1_g + EE, ln1_b + EE, r1, 0);
    // 14. h2 = silu(y @ W1^T) -> r3
    tgemm<<<tgrid(NWIN, FF), 256, TG_SMEM>>>(r1, ffn1_w + (size_t)FF * EE, ffn1_b + FF,
                                             r3, NWIN, FF, EE, EE, EE, FF, 1);
    // 15. f2 -> r2
    tgemm<<<tgrid(NWIN, EE), 256, TG_SMEM>>>(r3, ffn2_w + (size_t)EE * FF, ffn2_b + EE,
                                             r2, NWIN, EE, FF, FF, FF, EE, 0);
    // 16. y2 = LN2_l2(y + f2) -> r1
    add_ln_kernel<<<NWIN, 256>>>(r2, r1, ln2_g + EE, ln2_b + EE, r1, 0);
    // 17. head -> d_out
    head_kernel<<<(NWIN * OUTD + 255) / 256, 256>>>(r1, head_w, head_b, out);
}